// round 12
// baseline (speedup 1.0000x reference)
#include <cuda_runtime.h>
#include <cuda_bf16.h>

typedef unsigned int u32;
typedef unsigned long long u64;

#define Bb 64
#define Tt 512
#define Dd 1024
#define Hh 1024
#define Gblk 128

// ---------------- global scratch (allocation-free rule) ----------------
__device__ float g_Gx[(size_t)Tt * Bb * 2048];   // [t][b][n]
__device__ float g_Cx[(size_t)Tt * Bb * 1024];   // [t][b][n]
__device__ float g_h [Bb * Hh];                  // [b][c] fp32
__device__ float g_u [Bb * Hh];                  // [b][c]
__device__ float g_pA[(size_t)4 * Bb * 2048];    // [ksplit][b][n]
__device__ float g_pB[(size_t)8 * Bb * 1024];
__device__ __nv_bfloat16 g_hhi [Bb * Hh];        // h  split (written once per step)
__device__ __nv_bfloat16 g_hlo [Bb * Hh];
__device__ __nv_bfloat16 g_rhhi[Bb * Hh];        // r*h split
__device__ __nv_bfloat16 g_rhlo[Bb * Hh];
__device__ __nv_bfloat16 g_xhi[(size_t)Bb * Tt * Dd];
__device__ __nv_bfloat16 g_xlo[(size_t)Bb * Tt * Dd];
__device__ __nv_bfloat16 g_Whi[2048 * 2048];
__device__ __nv_bfloat16 g_Wlo[2048 * 2048];
__device__ __nv_bfloat16 g_Uhi[2048 * 1024];
__device__ __nv_bfloat16 g_Ulo[2048 * 1024];
__device__ u32 g_flags[Gblk * 32];               // 128B-padded arrival slots
__device__ u32 g_rel;                            // release word

// ---------------- helpers ----------------
__device__ __forceinline__ u32 ld_acq(const u32* p) {
    u32 v; asm volatile("ld.global.acquire.gpu.u32 %0, [%1];" : "=r"(v) : "l"(p)); return v;
}
__device__ __forceinline__ void st_rel(u32* p, u32 v) {
    asm volatile("st.global.release.gpu.u32 [%0], %1;" :: "l"(p), "r"(v) : "memory");
}
__device__ __forceinline__ float sigf(float x) { return __fdividef(1.0f, 1.0f + __expf(-x)); }
__device__ __forceinline__ float tanh_fast(float x) {
    float e = __expf(-2.0f * x);
    return __fdividef(1.0f - e, 1.0f + e);
}
__device__ __forceinline__ u32 smem_u32(const void* p) {
    u32 a; asm("{ .reg .u64 t; cvta.to.shared.u64 t, %1; cvt.u32.u64 %0, t; }" : "=r"(a) : "l"(p));
    return a;
}
__device__ __forceinline__ u32 pk(__nv_bfloat16 a, __nv_bfloat16 b) {
    __nv_bfloat162 t; t.x = a; t.y = b; return *reinterpret_cast<u32*>(&t);
}
__device__ __forceinline__ __nv_bfloat16 bfh(float x) { return __float2bfloat16_rn(x); }
__device__ __forceinline__ __nv_bfloat16 bfl(float x, __nv_bfloat16 h) {
    return __float2bfloat16_rn(x - __bfloat162float(h));
}
__device__ __forceinline__ void prefetch_l2(const void* p) {
    asm volatile("prefetch.global.L2 [%0];" :: "l"(p));
}

// ---------------- tensor-core primitives (baseline PTX, sm_80+) ----------------
__device__ __forceinline__ void ldm4(u32* r, u32 a) {
    asm volatile("ldmatrix.sync.aligned.m8n8.x4.shared.b16 {%0,%1,%2,%3}, [%4];"
        : "=r"(r[0]), "=r"(r[1]), "=r"(r[2]), "=r"(r[3]) : "r"(a));
}
__device__ __forceinline__ void ldm4t(u32* r, u32 a) {
    asm volatile("ldmatrix.sync.aligned.m8n8.x4.trans.shared.b16 {%0,%1,%2,%3}, [%4];"
        : "=r"(r[0]), "=r"(r[1]), "=r"(r[2]), "=r"(r[3]) : "r"(a));
}
__device__ __forceinline__ void mmaA(float* d, const u32* a, u32 b0, u32 b1) {
    asm volatile("mma.sync.aligned.m16n8k16.row.col.f32.bf16.bf16.f32 "
        "{%0,%1,%2,%3}, {%4,%5,%6,%7}, {%8,%9}, {%0,%1,%2,%3};"
        : "+f"(d[0]), "+f"(d[1]), "+f"(d[2]), "+f"(d[3])
        : "r"(a[0]), "r"(a[1]), "r"(a[2]), "r"(a[3]), "r"(b0), "r"(b1));
}
#define CPA16(dst, src) \
    asm volatile("cp.async.cg.shared.global [%0], [%1], 16;" :: "r"(dst), "l"(src))
#define CPA_COMMIT() asm volatile("cp.async.commit_group;")
#define CPA_WAIT1()  asm volatile("cp.async.wait_group 1;")
#define CPA_WAIT0()  asm volatile("cp.async.wait_group 0;")

// One k16 step for a warp tile m16 x n32: 3-term bf16 split => 12 HMMA.
__device__ __forceinline__ void mma_k16(float (&acc)[4][4], u32 aaddr, u32 alo_d,
                                        u32 baddr, u32 blo_d) {
    u32 ah[4], al[4];
    ldm4(ah, aaddr);
    ldm4(al, aaddr + alo_d);
#pragma unroll
    for (int p = 0; p < 2; p++) {
        u32 bh[4], bl[4];
        ldm4t(bh, baddr + p * 32);
        ldm4t(bl, baddr + p * 32 + blo_d);
        mmaA(acc[2 * p],     ah, bh[0], bh[1]);
        mmaA(acc[2 * p],     al, bh[0], bh[1]);
        mmaA(acc[2 * p],     ah, bl[0], bl[1]);
        mmaA(acc[2 * p + 1], ah, bh[2], bh[3]);
        mmaA(acc[2 * p + 1], al, bh[2], bh[3]);
        mmaA(acc[2 * p + 1], ah, bl[2], bl[3]);
    }
}

// ---------------- conversion kernels ----------------
__global__ void __launch_bounds__(256) conv_split(
    const float4* __restrict__ src, int which, int n4)
{
    int i = blockIdx.x * blockDim.x + threadIdx.x;
    if (i >= n4) return;
    u32* hi; u32* lo;
    if (which == 0)      { hi = (u32*)g_xhi; lo = (u32*)g_xlo; }
    else if (which == 1) { hi = (u32*)g_Whi; lo = (u32*)g_Wlo; }
    else                 { hi = (u32*)g_Uhi; lo = (u32*)g_Ulo; }
    float4 v = src[i];
    __nv_bfloat16 hx = bfh(v.x), hy = bfh(v.y), hz = bfh(v.z), hw = bfh(v.w);
    hi[2 * i]     = pk(hx, hy);
    hi[2 * i + 1] = pk(hz, hw);
    lo[2 * i]     = pk(bfl(v.x, hx), bfl(v.y, hy));
    lo[2 * i + 1] = pk(bfl(v.z, hz), bfl(v.w, hw));
}

__global__ void __launch_bounds__(256) copy_h0(const float* __restrict__ h0)
{
    int i = (blockIdx.x * blockDim.x + threadIdx.x) * 2;
    if (i >= Bb * Hh) return;
    float2 v = *reinterpret_cast<const float2*>(&h0[i]);
    *reinterpret_cast<float2*>(&g_h[i]) = v;
    __nv_bfloat16 h0b = bfh(v.x), h1b = bfh(v.y);
    *reinterpret_cast<u32*>(&g_hhi[i]) = pk(h0b, h1b);
    *reinterpret_cast<u32*>(&g_hlo[i]) = pk(bfl(v.x, h0b), bfl(v.y, h1b));
}

// ---------------- precompute (x-path) ----------------
// grid (48, 128): bx<32 -> W/Gx colblock (64 n), else U/Cx; by = group of 4 t.
// W chunk held in smem across the 4 timesteps (4x less W L2 traffic).
#define PRE_SMEM 73728

__global__ void __launch_bounds__(256) gemm_pre_tc(
    const float* __restrict__ Wb, const float* __restrict__ Ub)
{
    extern __shared__ char smp[];
    const u32 sb32 = smem_u32(smp);
    const int tid = threadIdx.x;
    const int cb = blockIdx.x, tg = blockIdx.y;
    const bool isW = cb < 32;
    const __nv_bfloat16* whi = isW ? g_Whi : g_Uhi;
    const __nv_bfloat16* wlo = isW ? g_Wlo : g_Ulo;
    const float* bia = isW ? Wb : Ub;
    float* outg = isW ? g_Gx : g_Cx;
    const int ldn = isW ? 2048 : 1024;
    const int n0  = (isW ? cb : cb - 32) * 64;

    const int lane = tid & 31, w = tid >> 5;
    const int mt = (w & 3) * 16, nh = (w >> 2) * 32;
    const int row = lane & 15, lh = lane >> 4;

    float acc[4][4][4];
#pragma unroll
    for (int tt = 0; tt < 4; tt++)
#pragma unroll
        for (int i = 0; i < 4; i++)
#pragma unroll
            for (int j = 0; j < 4; j++) acc[tt][i][j] = 0.0f;

    auto copyW = [&](int ch) {
        const int k0 = ch * 64;
        const u32 wbuf = sb32 + (ch & 1) * 18432;
#pragma unroll
        for (int j = 0; j < 4; j++) {
            int idx = j * 256 + tid;           // 0..1023
            int r = (idx >> 3) & 63, c8 = idx & 7;
            bool isLo = idx >= 512;
            const __nv_bfloat16* src = (isLo ? wlo : whi) + (size_t)(k0 + r) * ldn + n0 + c8 * 8;
            CPA16(wbuf + (isLo ? 9216 : 0) + r * 144 + c8 * 16, src);
        }
    };
    auto copyX = [&](int s) {                  // s = ch*4 + tt
        const int ch = s >> 2, t = tg * 4 + (s & 3);
        const int k0 = ch * 64;
        const u32 xbuf = sb32 + 36864 + (s & 1) * 18432;
#pragma unroll
        for (int j = 0; j < 4; j++) {
            int idx = j * 256 + tid;
            int r = (idx >> 3) & 63, c8 = idx & 7;
            bool isLo = idx >= 512;
            const __nv_bfloat16* src = (isLo ? g_xlo : g_xhi) + ((size_t)r * Tt + t) * Dd + k0 + c8 * 8;
            CPA16(xbuf + (isLo ? 9216 : 0) + r * 144 + c8 * 16, src);
        }
    };

    copyW(0); copyX(0); CPA_COMMIT();
    for (int s = 0; s < 64; s++) {
        const int ch = s >> 2, tt = s & 3;
        if (s + 1 < 64) {
            if (tt == 3) copyW(ch + 1);
            copyX(s + 1);
            CPA_COMMIT();
            CPA_WAIT1();
        } else CPA_WAIT0();
        __syncthreads();
        const u32 wbuf = sb32 + (ch & 1) * 18432;
        const u32 xbuf = sb32 + 36864 + (s & 1) * 18432;
        const u32 abase = xbuf + (mt + row) * 144 + lh * 16;
        const u32 bbase = wbuf + row * 144 + (nh + lh * 8) * 2;
#pragma unroll
        for (int k16 = 0; k16 < 4; k16++)
            mma_k16(acc[tt], abase + k16 * 32, 9216, bbase + k16 * 2304, 9216);
        __syncthreads();
    }

    // epilogue: + bias, write [t][b][n]
    const int r0 = lane >> 2, c0 = (lane & 3) * 2;
#pragma unroll
    for (int tt = 0; tt < 4; tt++) {
        const int t = tg * 4 + tt;
#pragma unroll
        for (int na = 0; na < 4; na++) {
            int col = n0 + nh + na * 8 + c0;
            float2 bv = *reinterpret_cast<const float2*>(&bia[col]);
            *reinterpret_cast<float2*>(&outg[((size_t)t * Bb + mt + r0) * ldn + col]) =
                make_float2(acc[tt][na][0] + bv.x, acc[tt][na][1] + bv.y);
            *reinterpret_cast<float2*>(&outg[((size_t)t * Bb + mt + r0 + 8) * ldn + col]) =
                make_float2(acc[tt][na][2] + bv.x, acc[tt][na][3] + bv.y);
        }
    }
}

// ---------------- persistent recurrence ----------------
// Phase A: 32 colblocks(64 n of 2048) x 4 ksplits(K=256).
// Phase B: 16 colblocks(64 n of 1024) x 8 ksplits(K=128).
// Weights resident in smem; h/rh staged via cp.async from pre-split bf16 gmem.
#define OFF_WAHI 0
#define OFF_WALO 36864
#define OFF_WBHI 73728
#define OFF_WBLO 92160
#define OFF_HT   110592
#define REC_SMEM 178176

__global__ void __launch_bounds__(256) gru_persist(float* __restrict__ out)
{
    extern __shared__ char smp[];
    const u32 sb32 = smem_u32(smp);
    const int tid = threadIdx.x, bx = blockIdx.x;
    const int lane = tid & 31, w = tid >> 5;
    const int mt = (w & 3) * 16, nh = (w >> 2) * 32;
    const int row = lane & 15, lh = lane >> 4;
    const int r0 = lane >> 2, c0 = (lane & 3) * 2;
    const int ca = bx & 31, sa = bx >> 5;   // phase A decomposition
    const int cbp = bx & 15, sbp = bx >> 4; // phase B decomposition

    // ---- one-time: load resident weight slices ----
    {
        const u32* wsh = reinterpret_cast<const u32*>(g_Whi);
        const u32* wsl = reinterpret_cast<const u32*>(g_Wlo);
        for (int i = tid; i < 256 * 32; i += 256) {
            int r = i >> 5, c = i & 31;
            size_t s = ((size_t)(Dd + sa * 256 + r) * 2048 + ca * 64) / 2 + c;
            *reinterpret_cast<u32*>(smp + OFF_WAHI + r * 144 + c * 4) = wsh[s];
            *reinterpret_cast<u32*>(smp + OFF_WALO + r * 144 + c * 4) = wsl[s];
        }
        const u32* ush = reinterpret_cast<const u32*>(g_Uhi);
        const u32* usl = reinterpret_cast<const u32*>(g_Ulo);
        for (int i = tid; i < 128 * 32; i += 256) {
            int r = i >> 5, c = i & 31;
            size_t s = ((size_t)(Dd + sbp * 128 + r) * 1024 + cbp * 64) / 2 + c;
            *reinterpret_cast<u32*>(smp + OFF_WBHI + r * 144 + c * 4) = ush[s];
            *reinterpret_cast<u32*>(smp + OFF_WBLO + r * 144 + c * 4) = usl[s];
        }
    }
    __syncthreads();

    const u32 base = ld_acq(&g_rel);
    u32 epoch = 0;

    // Contention-free barrier: per-block padded flag (plain release store),
    // block 0's warp 0 aggregates and publishes g_rel; others poll one word.
#define GRID_BAR()                                                            \
    do {                                                                      \
        __syncthreads();                                                      \
        epoch++;                                                              \
        if (w == 0) {                                                         \
            if (lane == 0) st_rel(&g_flags[bx * 32], base + epoch);           \
            if (bx == 0) {                                                    \
                for (;;) {                                                    \
                    u32 ok = 1;                                               \
                    _Pragma("unroll")                                         \
                    for (int j = 0; j < 4; j++) {                             \
                        u32 v = ld_acq(&g_flags[(lane + j * 32) * 32]);       \
                        ok &= (u32)(v - base) >= epoch;                       \
                    }                                                         \
                    if (__all_sync(0xffffffffu, ok)) break;                   \
                }                                                             \
                if (lane == 0) st_rel(&g_rel, base + epoch);                  \
            } else if (lane == 0) {                                           \
                while ((u32)(ld_acq(&g_rel) - base) < epoch) ;                \
            }                                                                 \
        }                                                                     \
        __syncthreads();                                                      \
    } while (0)

    const u32 abaseA = sb32 + OFF_HT + (mt + row) * 528 + lh * 16;  // stride 528
    const u32 abaseB = sb32 + OFF_HT + (mt + row) * 272 + lh * 16;  // stride 272
    const u32 baseA  = sb32 + OFF_WAHI + row * 144 + (nh + lh * 8) * 2;
    const u32 baseB  = sb32 + OFF_WBHI + row * 144 + (nh + lh * 8) * 2;

    for (int t = 0; t < Tt; ++t) {
        // L2 prefetch for the reduce phases
        if (tid < 32)
            prefetch_l2(reinterpret_cast<const char*>(g_Gx) +
                        ((size_t)t * Bb * 2048 + bx * 1024) * 4 + tid * 128);
        else if (tid < 48)
            prefetch_l2(reinterpret_cast<const char*>(g_Cx) +
                        ((size_t)t * Bb * 1024 + bx * 512) * 4 + (tid - 32) * 128);

        // ---------------- Phase A: gate partials ----------------
        {
            // stage h slice [64b x 256k] hi+lo: 4096 x 16B copies (j < 16!)
#pragma unroll
            for (int j = 0; j < 16; j++) {
                int idx = j * 256 + tid;            // 0..2047 hi, 2048..4095 lo
                int r = (idx >> 5) & 63, c16 = idx & 31;
                bool isLo = idx >= 2048;
                const __nv_bfloat16* src = (isLo ? g_hlo : g_hhi) + r * 1024 + sa * 256 + c16 * 8;
                CPA16(sb32 + OFF_HT + (isLo ? 64 * 528 : 0) + r * 528 + c16 * 16, src);
            }
            CPA_COMMIT(); CPA_WAIT0();
            __syncthreads();

            float acc[4][4];
#pragma unroll
            for (int i = 0; i < 4; i++)
#pragma unroll
                for (int j = 0; j < 4; j++) acc[i][j] = 0.0f;
#pragma unroll
            for (int k16 = 0; k16 < 16; k16++)
                mma_k16(acc, abaseA + k16 * 32, 64 * 528,
                        baseA + k16 * 2304, OFF_WALO - OFF_WAHI);
            float* pa = g_pA + (size_t)sa * (Bb * 2048);
#pragma unroll
            for (int na = 0; na < 4; na++) {
                int col = ca * 64 + nh + na * 8 + c0;
                *reinterpret_cast<float2*>(&pa[(size_t)(mt + r0) * 2048 + col]) =
                    make_float2(acc[na][0], acc[na][1]);
                *reinterpret_cast<float2*>(&pa[(size_t)(mt + r0 + 8) * 2048 + col]) =
                    make_float2(acc[na][2], acc[na][3]);
            }
        }
        GRID_BAR();

        // ---------------- A-reduce: sigmoid; split rh once ----------------
        {
            const int flat = bx * 1024 + tid * 4;   // = b*2048 + n
            const int b = flat >> 11, n = flat & 2047;
            float4 a = *reinterpret_cast<const float4*>(&g_Gx[(size_t)t * (Bb * 2048) + flat]);
#pragma unroll
            for (int s = 0; s < 4; s++) {
                float4 p = *reinterpret_cast<const float4*>(&g_pA[(size_t)s * (Bb * 2048) + flat]);
                a.x += p.x; a.y += p.y; a.z += p.z; a.w += p.w;
            }
            float4 g;
            g.x = sigf(a.x); g.y = sigf(a.y); g.z = sigf(a.z); g.w = sigf(a.w);
            if (n < 1024) {
                float4 h4 = *reinterpret_cast<const float4*>(&g_h[b * 1024 + n]);
                float v0 = g.x * h4.x, v1 = g.y * h4.y, v2 = g.z * h4.z, v3 = g.w * h4.w;
                __nv_bfloat16 h0b = bfh(v0), h1b = bfh(v1), h2b = bfh(v2), h3b = bfh(v3);
                *reinterpret_cast<uint2*>(&g_rhhi[b * 1024 + n]) =
                    make_uint2(pk(h0b, h1b), pk(h2b, h3b));
                *reinterpret_cast<uint2*>(&g_rhlo[b * 1024 + n]) =
                    make_uint2(pk(bfl(v0, h0b), bfl(v1, h1b)), pk(bfl(v2, h2b), bfl(v3, h3b)));
            } else {
                *reinterpret_cast<float4*>(&g_u[b * 1024 + (n - 1024)]) = g;
            }
        }
        GRID_BAR();

        // ---------------- Phase B: candidate partials ----------------
        {
            // stage rh slice [64b x 128k] hi+lo: 2048 x 16B copies (j < 8!)
#pragma unroll
            for (int j = 0; j < 8; j++) {
                int idx = j * 256 + tid;            // 0..1023 hi, 1024..2047 lo
                int r = (idx >> 4) & 63, c16 = idx & 15;
                bool isLo = idx >= 1024;
                const __nv_bfloat16* src = (isLo ? g_rhlo : g_rhhi) + r * 1024 + sbp * 128 + c16 * 8;
                CPA16(sb32 + OFF_HT + (isLo ? 64 * 272 : 0) + r * 272 + c16 * 16, src);
            }
            CPA_COMMIT(); CPA_WAIT0();
            __syncthreads();

            float acc[4][4];
#pragma unroll
            for (int i = 0; i < 4; i++)
#pragma unroll
                for (int j = 0; j < 4; j++) acc[i][j] = 0.0f;
#pragma unroll
            for (int k16 = 0; k16 < 8; k16++)
                mma_k16(acc, abaseB + k16 * 32, 64 * 272,
                        baseB + k16 * 2304, OFF_WBLO - OFF_WBHI);
            float* pb = g_pB + (size_t)sbp * (Bb * 1024);
#pragma unroll
            for (int na = 0; na < 4; na++) {
                int col = cbp * 64 + nh + na * 8 + c0;
                *reinterpret_cast<float2*>(&pb[(size_t)(mt + r0) * 1024 + col]) =
                    make_float2(acc[na][0], acc[na][1]);
                *reinterpret_cast<float2*>(&pb[(size_t)(mt + r0 + 8) * 1024 + col]) =
                    make_float2(acc[na][2], acc[na][3]);
            }
        }
        GRID_BAR();

        // ---------------- B-reduce: tanh + state update; split h ----------------
        {
            const int flat = bx * 512 + tid * 2;    // = b*1024 + n
            const int b = flat >> 10, n = flat & 1023;
            float2 a = *reinterpret_cast<const float2*>(&g_Cx[(size_t)t * (Bb * 1024) + flat]);
#pragma unroll
            for (int s = 0; s < 8; s++) {
                float2 p = *reinterpret_cast<const float2*>(&g_pB[(size_t)s * (Bb * 1024) + flat]);
                a.x += p.x; a.y += p.y;
            }
            float2 u2 = *reinterpret_cast<const float2*>(&g_u[flat]);
            float2 h2 = *reinterpret_cast<const float2*>(&g_h[flat]);
            float2 hn;
            hn.x = u2.x * h2.x + (1.0f - u2.x) * tanh_fast(a.x);
            hn.y = u2.y * h2.y + (1.0f - u2.y) * tanh_fast(a.y);
            *reinterpret_cast<float2*>(&g_h[flat]) = hn;
            __nv_bfloat16 h0b = bfh(hn.x), h1b = bfh(hn.y);
            *reinterpret_cast<u32*>(&g_hhi[flat]) = pk(h0b, h1b);
            *reinterpret_cast<u32*>(&g_hlo[flat]) = pk(bfl(hn.x, h0b), bfl(hn.y, h1b));
            *reinterpret_cast<float2*>(&out[((size_t)b * Tt + t) * 1024 + n]) = hn;
        }
        GRID_BAR();
    }
#undef GRID_BAR
}

extern "C" void kernel_launch(void* const* d_in, const int* in_sizes, int n_in,
                              void* d_out, int out_size)
{
    const float* x  = (const float*)d_in[0];
    const float* h0 = (const float*)d_in[1];
    const float* W  = (const float*)d_in[2];
    const float* Wb = (const float*)d_in[3];
    const float* U  = (const float*)d_in[4];
    const float* Ub = (const float*)d_in[5];
    float* out = (float*)d_out;

    cudaFuncSetAttribute(gemm_pre_tc, cudaFuncAttributeMaxDynamicSharedMemorySize, PRE_SMEM);
    cudaFuncSetAttribute(gru_persist, cudaFuncAttributeMaxDynamicSharedMemorySize, REC_SMEM);

    // one-time fp32 -> bf16 hi/lo splits
    conv_split<<<(Bb * Tt * Dd / 4 + 255) / 256, 256>>>((const float4*)x, 0, Bb * Tt * Dd / 4);
    conv_split<<<(2048 * 2048 / 4 + 255) / 256, 256>>>((const float4*)W, 1, 2048 * 2048 / 4);
    conv_split<<<(2048 * 1024 / 4 + 255) / 256, 256>>>((const float4*)U, 2, 2048 * 1024 / 4);

    copy_h0<<<Bb * Hh / 512, 256>>>(h0);

    // x-path precompute: Gx[t][b][n], Cx[t][b][n]
    gemm_pre_tc<<<dim3(48, 128), 256, PRE_SMEM>>>(Wb, Ub);

    // persistent recurrence
    gru_persist<<<Gblk, 256, REC_SMEM>>>(out);
}

// round 13
// speedup vs baseline: 1.6326x; 1.6326x over previous
#include <cuda_runtime.h>
#include <cuda_bf16.h>

typedef unsigned int u32;
typedef unsigned long long u64;

#define Bb 64
#define Tt 512
#define Dd 1024
#define Hh 1024
#define Gblk 128

// ---------------- global scratch (allocation-free rule) ----------------
__device__ float g_Gx[(size_t)Tt * Bb * 2048];   // [t][b][n]
__device__ float g_Cx[(size_t)Tt * Bb * 1024];   // [t][b][n]
__device__ float g_h [Bb * Hh];                  // [b][c] fp32
__device__ float g_rh[Bb * Hh];
__device__ float g_u [Bb * Hh];
__device__ float g_pA[(size_t)4 * Bb * 2048];    // [ksplit][b][n]
__device__ float g_pB[(size_t)8 * Bb * 1024];
__device__ __nv_bfloat16 g_xhi[(size_t)Bb * Tt * Dd];
__device__ __nv_bfloat16 g_xlo[(size_t)Bb * Tt * Dd];
__device__ __nv_bfloat16 g_Whi[2048 * 2048];
__device__ __nv_bfloat16 g_Wlo[2048 * 2048];
__device__ __nv_bfloat16 g_Uhi[2048 * 1024];
__device__ __nv_bfloat16 g_Ulo[2048 * 1024];
__device__ unsigned g_arrive;                    // monotonic barrier counter

// ---------------- helpers ----------------
__device__ __forceinline__ unsigned ld_acq(const unsigned* p) {
    unsigned v; asm volatile("ld.global.acquire.gpu.u32 %0, [%1];" : "=r"(v) : "l"(p)); return v;
}
__device__ __forceinline__ void red_release(unsigned* p) {
    asm volatile("red.release.gpu.global.add.u32 [%0], 1;" :: "l"(p) : "memory");
}
__device__ __forceinline__ float sigf(float x) { return __fdividef(1.0f, 1.0f + __expf(-x)); }
__device__ __forceinline__ float tanh_fast(float x) {
    float e = __expf(-2.0f * x);
    return __fdividef(1.0f - e, 1.0f + e);
}
__device__ __forceinline__ u32 smem_u32(const void* p) {
    u32 a; asm("{ .reg .u64 t; cvta.to.shared.u64 t, %1; cvt.u32.u64 %0, t; }" : "=r"(a) : "l"(p));
    return a;
}
__device__ __forceinline__ u32 pk(__nv_bfloat16 a, __nv_bfloat16 b) {
    __nv_bfloat162 t; t.x = a; t.y = b; return *reinterpret_cast<u32*>(&t);
}
__device__ __forceinline__ __nv_bfloat16 bfh(float x) { return __float2bfloat16_rn(x); }
__device__ __forceinline__ __nv_bfloat16 bfl(float x, __nv_bfloat16 h) {
    return __float2bfloat16_rn(x - __bfloat162float(h));
}
__device__ __forceinline__ void prefetch_l2(const void* p) {
    asm volatile("prefetch.global.L2 [%0];" :: "l"(p));
}

// ---------------- tensor-core primitives (baseline PTX, sm_80+) ----------------
__device__ __forceinline__ void ldm4(u32* r, u32 a) {
    asm volatile("ldmatrix.sync.aligned.m8n8.x4.shared.b16 {%0,%1,%2,%3}, [%4];"
        : "=r"(r[0]), "=r"(r[1]), "=r"(r[2]), "=r"(r[3]) : "r"(a));
}
__device__ __forceinline__ void ldm4t(u32* r, u32 a) {
    asm volatile("ldmatrix.sync.aligned.m8n8.x4.trans.shared.b16 {%0,%1,%2,%3}, [%4];"
        : "=r"(r[0]), "=r"(r[1]), "=r"(r[2]), "=r"(r[3]) : "r"(a));
}
__device__ __forceinline__ void mmaA(float* d, const u32* a, u32 b0, u32 b1) {
    asm volatile("mma.sync.aligned.m16n8k16.row.col.f32.bf16.bf16.f32 "
        "{%0,%1,%2,%3}, {%4,%5,%6,%7}, {%8,%9}, {%0,%1,%2,%3};"
        : "+f"(d[0]), "+f"(d[1]), "+f"(d[2]), "+f"(d[3])
        : "r"(a[0]), "r"(a[1]), "r"(a[2]), "r"(a[3]), "r"(b0), "r"(b1));
}
#define CPA16(dst, src) \
    asm volatile("cp.async.cg.shared.global [%0], [%1], 16;" :: "r"(dst), "l"(src))
#define CPA_COMMIT() asm volatile("cp.async.commit_group;")
#define CPA_WAIT1()  asm volatile("cp.async.wait_group 1;")
#define CPA_WAIT0()  asm volatile("cp.async.wait_group 0;")

// One k16 step for a warp tile m16 x n32: 3-term bf16 split => 12 HMMA.
__device__ __forceinline__ void mma_k16(float (&acc)[4][4], u32 aaddr, u32 alo_d,
                                        u32 baddr, u32 blo_d) {
    u32 ah[4], al[4];
    ldm4(ah, aaddr);
    ldm4(al, aaddr + alo_d);
#pragma unroll
    for (int p = 0; p < 2; p++) {
        u32 bh[4], bl[4];
        ldm4t(bh, baddr + p * 32);
        ldm4t(bl, baddr + p * 32 + blo_d);
        mmaA(acc[2 * p],     ah, bh[0], bh[1]);
        mmaA(acc[2 * p],     al, bh[0], bh[1]);
        mmaA(acc[2 * p],     ah, bl[0], bl[1]);
        mmaA(acc[2 * p + 1], ah, bh[2], bh[3]);
        mmaA(acc[2 * p + 1], al, bh[2], bh[3]);
        mmaA(acc[2 * p + 1], ah, bl[2], bl[3]);
    }
}

// ---------------- conversion kernels ----------------
__global__ void __launch_bounds__(256) conv_split(
    const float4* __restrict__ src, int which, int n4)
{
    int i = blockIdx.x * blockDim.x + threadIdx.x;
    if (i >= n4) return;
    u32* hi; u32* lo;
    if (which == 0)      { hi = (u32*)g_xhi; lo = (u32*)g_xlo; }
    else if (which == 1) { hi = (u32*)g_Whi; lo = (u32*)g_Wlo; }
    else                 { hi = (u32*)g_Uhi; lo = (u32*)g_Ulo; }
    float4 v = src[i];
    __nv_bfloat16 hx = bfh(v.x), hy = bfh(v.y), hz = bfh(v.z), hw = bfh(v.w);
    hi[2 * i]     = pk(hx, hy);
    hi[2 * i + 1] = pk(hz, hw);
    lo[2 * i]     = pk(bfl(v.x, hx), bfl(v.y, hy));
    lo[2 * i + 1] = pk(bfl(v.z, hz), bfl(v.w, hw));
}

__global__ void __launch_bounds__(256) copy_h0(const float* __restrict__ h0)
{
    int i = blockIdx.x * blockDim.x + threadIdx.x;
    if (i < Bb * Hh) g_h[i] = h0[i];
}

// ---------------- precompute (x-path), t-batched ----------------
// grid (48, 128): bx<32 -> W/Gx colblock (64 n), else U/Cx; by = group of 4 t.
// W chunk held in smem across the 4 timesteps (4x less W L2 traffic).
#define PRE_SMEM 73728

__global__ void __launch_bounds__(256) gemm_pre_tc(
    const float* __restrict__ Wb, const float* __restrict__ Ub)
{
    extern __shared__ char smp[];
    const u32 sb32 = smem_u32(smp);
    const int tid = threadIdx.x;
    const int cb = blockIdx.x, tg = blockIdx.y;
    const bool isW = cb < 32;
    const __nv_bfloat16* whi = isW ? g_Whi : g_Uhi;
    const __nv_bfloat16* wlo = isW ? g_Wlo : g_Ulo;
    const float* bia = isW ? Wb : Ub;
    float* outg = isW ? g_Gx : g_Cx;
    const int ldn = isW ? 2048 : 1024;
    const int n0  = (isW ? cb : cb - 32) * 64;

    const int lane = tid & 31, w = tid >> 5;
    const int mt = (w & 3) * 16, nh = (w >> 2) * 32;
    const int row = lane & 15, lh = lane >> 4;

    float acc[4][4][4];
#pragma unroll
    for (int tt = 0; tt < 4; tt++)
#pragma unroll
        for (int i = 0; i < 4; i++)
#pragma unroll
            for (int j = 0; j < 4; j++) acc[tt][i][j] = 0.0f;

    auto copyW = [&](int ch) {
        const int k0 = ch * 64;
        const u32 wbuf = sb32 + (ch & 1) * 18432;
#pragma unroll
        for (int j = 0; j < 4; j++) {
            int idx = j * 256 + tid;           // 0..1023
            int r = (idx >> 3) & 63, c8 = idx & 7;
            bool isLo = idx >= 512;
            const __nv_bfloat16* src = (isLo ? wlo : whi) + (size_t)(k0 + r) * ldn + n0 + c8 * 8;
            CPA16(wbuf + (isLo ? 9216 : 0) + r * 144 + c8 * 16, src);
        }
    };
    auto copyX = [&](int s) {                  // s = ch*4 + tt
        const int ch = s >> 2, t = tg * 4 + (s & 3);
        const int k0 = ch * 64;
        const u32 xbuf = sb32 + 36864 + (s & 1) * 18432;
#pragma unroll
        for (int j = 0; j < 4; j++) {
            int idx = j * 256 + tid;
            int r = (idx >> 3) & 63, c8 = idx & 7;
            bool isLo = idx >= 512;
            const __nv_bfloat16* src = (isLo ? g_xlo : g_xhi) + ((size_t)r * Tt + t) * Dd + k0 + c8 * 8;
            CPA16(xbuf + (isLo ? 9216 : 0) + r * 144 + c8 * 16, src);
        }
    };

    copyW(0); copyX(0); CPA_COMMIT();
    for (int s = 0; s < 64; s++) {
        const int ch = s >> 2, tt = s & 3;
        if (s + 1 < 64) {
            if (tt == 3) copyW(ch + 1);
            copyX(s + 1);
            CPA_COMMIT();
            CPA_WAIT1();
        } else CPA_WAIT0();
        __syncthreads();
        const u32 wbuf = sb32 + (ch & 1) * 18432;
        const u32 xbuf = sb32 + 36864 + (s & 1) * 18432;
        const u32 abase = xbuf + (mt + row) * 144 + lh * 16;
        const u32 bbase = wbuf + row * 144 + (nh + lh * 8) * 2;
#pragma unroll
        for (int k16 = 0; k16 < 4; k16++)
            mma_k16(acc[tt], abase + k16 * 32, 9216, bbase + k16 * 2304, 9216);
        __syncthreads();
    }

    // epilogue: + bias, write [t][b][n]
    const int r0 = lane >> 2, c0 = (lane & 3) * 2;
#pragma unroll
    for (int tt = 0; tt < 4; tt++) {
        const int t = tg * 4 + tt;
#pragma unroll
        for (int na = 0; na < 4; na++) {
            int col = n0 + nh + na * 8 + c0;
            float2 bv = *reinterpret_cast<const float2*>(&bia[col]);
            *reinterpret_cast<float2*>(&outg[((size_t)t * Bb + mt + r0) * ldn + col]) =
                make_float2(acc[tt][na][0] + bv.x, acc[tt][na][1] + bv.y);
            *reinterpret_cast<float2*>(&outg[((size_t)t * Bb + mt + r0 + 8) * ldn + col]) =
                make_float2(acc[tt][na][2] + bv.x, acc[tt][na][3] + bv.y);
        }
    }
}

// ---------------- persistent recurrence (R10-proven skeleton) ----------------
// Phase A: 32 colblocks(64 n of 2048) x 4 ksplits(K=256).
// Phase B: 16 colblocks(64 n of 1024) x 8 ksplits(K=128).
// Weights resident in smem; h/rh staged fp32->bf16 hi/lo per step (coalesced).
#define OFF_WAHI 0
#define OFF_WALO 36864
#define OFF_WBHI 73728
#define OFF_WBLO 92160
#define OFF_HHI  110592
#define OFF_HLO  144384
#define REC_SMEM 178176

__global__ void __launch_bounds__(256) gru_persist(float* __restrict__ out)
{
    extern __shared__ char smp[];
    const u32 sb32 = smem_u32(smp);
    const int tid = threadIdx.x, bx = blockIdx.x;
    const int lane = tid & 31, w = tid >> 5;
    const int mt = (w & 3) * 16, nh = (w >> 2) * 32;
    const int row = lane & 15, lh = lane >> 4;
    const int r0 = lane >> 2, c0 = (lane & 3) * 2;
    const int ca = bx & 31, sa = bx >> 5;   // phase A decomposition
    const int cbp = bx & 15, sbp = bx >> 4; // phase B decomposition

    // ---- one-time: load resident weight slices ----
    {
        const u32* wsh = reinterpret_cast<const u32*>(g_Whi);
        const u32* wsl = reinterpret_cast<const u32*>(g_Wlo);
        for (int i = tid; i < 256 * 32; i += 256) {
            int r = i >> 5, c = i & 31;
            size_t s = ((size_t)(Dd + sa * 256 + r) * 2048 + ca * 64) / 2 + c;
            *reinterpret_cast<u32*>(smp + OFF_WAHI + r * 144 + c * 4) = wsh[s];
            *reinterpret_cast<u32*>(smp + OFF_WALO + r * 144 + c * 4) = wsl[s];
        }
        const u32* ush = reinterpret_cast<const u32*>(g_Uhi);
        const u32* usl = reinterpret_cast<const u32*>(g_Ulo);
        for (int i = tid; i < 128 * 32; i += 256) {
            int r = i >> 5, c = i & 31;
            size_t s = ((size_t)(Dd + sbp * 128 + r) * 1024 + cbp * 64) / 2 + c;
            *reinterpret_cast<u32*>(smp + OFF_WBHI + r * 144 + c * 4) = ush[s];
            *reinterpret_cast<u32*>(smp + OFF_WBLO + r * 144 + c * 4) = usl[s];
        }
    }
    __syncthreads();

    const unsigned basec = ld_acq(&g_arrive);
    unsigned epoch = 0;

    // R10-proven barrier: single red.release arrival + acquire poll.
#define GRID_BAR()                                                           \
    do {                                                                     \
        __syncthreads();                                                     \
        epoch++;                                                             \
        if (tid == 0) {                                                      \
            red_release(&g_arrive);                                          \
            while ((unsigned)(ld_acq(&g_arrive) - basec) < epoch * Gblk) ;   \
        }                                                                    \
        __syncthreads();                                                     \
    } while (0)

    // Coalesced staging: warp reads contiguous float4 runs from one h row,
    // splits to bf16 hi/lo, stores contiguous 8B runs. Layout identical to
    // R10 (row stride 528B, lo tile at +33792) so MMA addressing unchanged.
    auto stage_h = [&](const float* src, int kbase, int lgF4) {
        const int iters = (lgF4 == 6) ? 16 : 8;
        const int mask = (1 << lgF4) - 1;
        for (int j = 0; j < iters; j++) {
            int idx = j * 256 + tid;
            int r = idx >> lgF4, c4 = idx & mask;
            float4 a = *reinterpret_cast<const float4*>(src + (size_t)r * 1024 + kbase + c4 * 4);
            __nv_bfloat16 h0 = bfh(a.x), h1 = bfh(a.y), h2 = bfh(a.z), h3 = bfh(a.w);
            *reinterpret_cast<uint2*>(smp + OFF_HHI + r * 528 + c4 * 8) =
                make_uint2(pk(h0, h1), pk(h2, h3));
            *reinterpret_cast<uint2*>(smp + OFF_HLO + r * 528 + c4 * 8) =
                make_uint2(pk(bfl(a.x, h0), bfl(a.y, h1)), pk(bfl(a.z, h2), bfl(a.w, h3)));
        }
    };

    const u32 abase0 = sb32 + OFF_HHI + (mt + row) * 528 + lh * 16;
    const u32 baseA  = sb32 + OFF_WAHI + row * 144 + (nh + lh * 8) * 2;
    const u32 baseB  = sb32 + OFF_WBHI + row * 144 + (nh + lh * 8) * 2;

    for (int t = 0; t < Tt; ++t) {
        // L2 prefetch for the reduce phases
        if (tid < 32)
            prefetch_l2(reinterpret_cast<const char*>(g_Gx) +
                        ((size_t)t * Bb * 2048 + bx * 1024) * 4 + tid * 128);
        else if (tid < 48)
            prefetch_l2(reinterpret_cast<const char*>(g_Cx) +
                        ((size_t)t * Bb * 1024 + bx * 512) * 4 + (tid - 32) * 128);

        // ---------------- Phase A: gate partials ----------------
        {
            stage_h(g_h, sa * 256, 6);
            __syncthreads();
            float acc[4][4];
#pragma unroll
            for (int i = 0; i < 4; i++)
#pragma unroll
                for (int j = 0; j < 4; j++) acc[i][j] = 0.0f;
#pragma unroll
            for (int k16 = 0; k16 < 16; k16++)
                mma_k16(acc, abase0 + k16 * 32, OFF_HLO - OFF_HHI,
                        baseA + k16 * 2304, OFF_WALO - OFF_WAHI);
            float* pa = g_pA + (size_t)sa * (Bb * 2048);
#pragma unroll
            for (int na = 0; na < 4; na++) {
                int col = ca * 64 + nh + na * 8 + c0;
                *reinterpret_cast<float2*>(&pa[(size_t)(mt + r0) * 2048 + col]) =
                    make_float2(acc[na][0], acc[na][1]);
                *reinterpret_cast<float2*>(&pa[(size_t)(mt + r0 + 8) * 2048 + col]) =
                    make_float2(acc[na][2], acc[na][3]);
            }
        }
        GRID_BAR();

        // ---------------- A-reduce: sigmoid gates ----------------
        {
            const int flat = bx * 1024 + tid * 4;   // = b*2048 + n
            float4 a = *reinterpret_cast<const float4*>(&g_Gx[(size_t)t * (Bb * 2048) + flat]);
#pragma unroll
            for (int s = 0; s < 4; s++) {
                float4 p = *reinterpret_cast<const float4*>(&g_pA[(size_t)s * (Bb * 2048) + flat]);
                a.x += p.x; a.y += p.y; a.z += p.z; a.w += p.w;
            }
            float4 g;
            g.x = sigf(a.x); g.y = sigf(a.y); g.z = sigf(a.z); g.w = sigf(a.w);
            const int hidx = (bx >> 1) * 1024 + tid * 4;
            if (bx & 1) {
                *reinterpret_cast<float4*>(&g_u[hidx]) = g;
            } else {
                float4 h4 = *reinterpret_cast<const float4*>(&g_h[hidx]);
                *reinterpret_cast<float4*>(&g_rh[hidx]) =
                    make_float4(g.x * h4.x, g.y * h4.y, g.z * h4.z, g.w * h4.w);
            }
        }
        GRID_BAR();

        // ---------------- Phase B: candidate partials ----------------
        {
            stage_h(g_rh, sbp * 128, 5);
            __syncthreads();
            float acc[4][4];
#pragma unroll
            for (int i = 0; i < 4; i++)
#pragma unroll
                for (int j = 0; j < 4; j++) acc[i][j] = 0.0f;
#pragma unroll
            for (int k16 = 0; k16 < 8; k16++)
                mma_k16(acc, abase0 + k16 * 32, OFF_HLO - OFF_HHI,
                        baseB + k16 * 2304, OFF_WBLO - OFF_WBHI);
            float* pb = g_pB + (size_t)sbp * (Bb * 1024);
#pragma unroll
            for (int na = 0; na < 4; na++) {
                int col = cbp * 64 + nh + na * 8 + c0;
                *reinterpret_cast<float2*>(&pb[(size_t)(mt + r0) * 1024 + col]) =
                    make_float2(acc[na][0], acc[na][1]);
                *reinterpret_cast<float2*>(&pb[(size_t)(mt + r0 + 8) * 1024 + col]) =
                    make_float2(acc[na][2], acc[na][3]);
            }
        }
        GRID_BAR();

        // ---------------- B-reduce: tanh + state update ----------------
        {
            const int flat = bx * 512 + tid * 2;    // = b*1024 + n
            float2 a = *reinterpret_cast<const float2*>(&g_Cx[(size_t)t * (Bb * 1024) + flat]);
#pragma unroll
            for (int s = 0; s < 8; s++) {
                float2 p = *reinterpret_cast<const float2*>(&g_pB[(size_t)s * (Bb * 1024) + flat]);
                a.x += p.x; a.y += p.y;
            }
            float2 u2 = *reinterpret_cast<const float2*>(&g_u[flat]);
            float2 h2 = *reinterpret_cast<const float2*>(&g_h[flat]);
            float2 hn;
            hn.x = u2.x * h2.x + (1.0f - u2.x) * tanh_fast(a.x);
            hn.y = u2.y * h2.y + (1.0f - u2.y) * tanh_fast(a.y);
            *reinterpret_cast<float2*>(&g_h[flat]) = hn;
            const int b = flat >> 10, n = flat & 1023;
            *reinterpret_cast<float2*>(&out[((size_t)b * Tt + t) * 1024 + n]) = hn;
        }
        GRID_BAR();
    }
#undef GRID_BAR
}

extern "C" void kernel_launch(void* const* d_in, const int* in_sizes, int n_in,
                              void* d_out, int out_size)
{
    const float* x  = (const float*)d_in[0];
    const float* h0 = (const float*)d_in[1];
    const float* W  = (const float*)d_in[2];
    const float* Wb = (const float*)d_in[3];
    const float* U  = (const float*)d_in[4];
    const float* Ub = (const float*)d_in[5];
    float* out = (float*)d_out;

    cudaFuncSetAttribute(gemm_pre_tc, cudaFuncAttributeMaxDynamicSharedMemorySize, PRE_SMEM);
    cudaFuncSetAttribute(gru_persist, cudaFuncAttributeMaxDynamicSharedMemorySize, REC_SMEM);

    // one-time fp32 -> bf16 hi/lo splits
    conv_split<<<(Bb * Tt * Dd / 4 + 255) / 256, 256>>>((const float4*)x, 0, Bb * Tt * Dd / 4);
    conv_split<<<(2048 * 2048 / 4 + 255) / 256, 256>>>((const float4*)W, 1, 2048 * 2048 / 4);
    conv_split<<<(2048 * 1024 / 4 + 255) / 256, 256>>>((const float4*)U, 2, 2048 * 1024 / 4);

    copy_h0<<<(Bb * Hh) / 256, 256>>>(h0);

    // x-path precompute: Gx[t][b][n], Cx[t][b][n]  (t-batched x4)
    gemm_pre_tc<<<dim3(48, 128), 256, PRE_SMEM>>>(Wb, Ub);

    // persistent recurrence
    gru_persist<<<Gblk, 256, REC_SMEM>>>(out);
}